// round 8
// baseline (speedup 1.0000x reference)
#include <cuda_runtime.h>
#include <math.h>
#include <stdint.h>

#define BB 2
#define SS 4096
#define DD 768
#define NH 12
#define HD 64
#define WIN 256

typedef unsigned long long ull;

// scratch: q/k/v in [B,H,S,HD] layout
__device__ float g_q[BB*NH*SS*HD];
__device__ float g_k[BB*NH*SS*HD];
__device__ float g_v[BB*NH*SS*HD];

// ---------------------------------------------------------------------------
// packed f32x2 helpers
// ---------------------------------------------------------------------------
__device__ __forceinline__ ull pk2(float a, float b) {
    ull r;
    asm("mov.b64 %0, {%1,%2};" : "=l"(r) : "f"(a), "f"(b));
    return r;
}
__device__ __forceinline__ void upk2(float& a, float& b, ull v) {
    asm("mov.b64 {%0,%1}, %2;" : "=f"(a), "=f"(b) : "l"(v));
}
__device__ __forceinline__ ull ffma2(ull a, ull b, ull c) {
    ull d;
    asm("fma.rn.f32x2 %0, %1, %2, %3;" : "=l"(d) : "l"(a), "l"(b), "l"(c));
    return d;
}

// fast exp on the FMA pipe
__device__ __forceinline__ float expfast(float x) {
    float z = x * 1.4426950408889634f;
    z = fmaxf(z, -126.0f);
    float t = z + 12582912.0f;
    int   ni = __float_as_int(t) - 0x4B400000;
    float n = t - 12582912.0f;
    float r = z - n;
    const float c6 = 1.5403530393381609e-4f;
    const float c5 = 1.3333558146428443e-3f;
    const float c4 = 9.6181291076284772e-3f;
    const float c3 = 5.5504108664821580e-2f;
    const float c2 = 2.4022650695910072e-1f;
    const float c1 = 6.9314718055994531e-1f;
    float p = fmaf(c6, r, c5);
    p = fmaf(p, r, c4);
    p = fmaf(p, r, c3);
    p = fmaf(p, r, c2);
    p = fmaf(p, r, c1);
    p = fmaf(p, r, 1.0f);
    float sc = __int_as_float((ni + 127) << 23);
    return p * sc;
}

// ---------------------------------------------------------------------------
// Fused QKV GEMM: 128x128x16 tile, 256 threads, 8x8 microtile (1.0 B/MAC).
// ---------------------------------------------------------------------------
__global__ __launch_bounds__(256) void qkv_gemm3(
    const float* __restrict__ A,
    const float* __restrict__ Wq, const float* __restrict__ Wk,
    const float* __restrict__ Wv,
    const float* __restrict__ bq, const float* __restrict__ bk,
    const float* __restrict__ bv,
    float* __restrict__ dq, float* __restrict__ dk, float* __restrict__ dv)
{
    __shared__ float As[16 * 132];       // [k][m] transposed
    __shared__ float Bs[16 * 132];       // [k][n] natural

    const int z = blockIdx.z;
    const float* __restrict__ W    = (z == 0) ? Wq : ((z == 1) ? Wk : Wv);
    const float* __restrict__ bias = (z == 0) ? bq : ((z == 1) ? bk : bv);
    float* __restrict__ dst        = (z == 0) ? dq : ((z == 1) ? dk : dv);
    const float scale              = (z == 0) ? 0.125f : 1.0f;

    const int tid = threadIdx.x;
    const int bm  = blockIdx.y * 128;
    const int bn  = blockIdx.x * 128;
    const int ty  = tid >> 4;            // 0..15: rows ty*8..+7
    const int tx  = tid & 15;            // 0..15: cols tx*8..+7
    const int ar  = tid >> 2;            // 0..63
    const int ak  = (tid & 3) << 2;      // 0,4,8,12
    const int bk_ = tid >> 4;            // 0..15
    const int bn8 = (tid & 15) << 3;     // 0..120

    ull acc2[4][8];                      // 4 row-pairs x 8 cols
    #pragma unroll
    for (int i = 0; i < 4; i++)
        #pragma unroll
        for (int j = 0; j < 8; j++) acc2[i][j] = 0ull;

    for (int kt = 0; kt < DD; kt += 16) {
        float4 a0 = *(const float4*)(A + (size_t)(bm + ar) * DD + kt + ak);
        float4 a1 = *(const float4*)(A + (size_t)(bm + ar + 64) * DD + kt + ak);
        float4 b0 = *(const float4*)(W + (size_t)(kt + bk_) * DD + bn + bn8);
        float4 b1 = *(const float4*)(W + (size_t)(kt + bk_) * DD + bn + bn8 + 4);
        __syncthreads();
        As[(ak + 0) * 132 + ar]      = a0.x;
        As[(ak + 1) * 132 + ar]      = a0.y;
        As[(ak + 2) * 132 + ar]      = a0.z;
        As[(ak + 3) * 132 + ar]      = a0.w;
        As[(ak + 0) * 132 + ar + 64] = a1.x;
        As[(ak + 1) * 132 + ar + 64] = a1.y;
        As[(ak + 2) * 132 + ar + 64] = a1.z;
        As[(ak + 3) * 132 + ar + 64] = a1.w;
        *(float4*)&Bs[bk_ * 132 + bn8]     = b0;
        *(float4*)&Bs[bk_ * 132 + bn8 + 4] = b1;
        __syncthreads();
        #pragma unroll
        for (int kk = 0; kk < 16; kk++) {
            float4 af0 = *(float4*)&As[kk * 132 + ty * 8];
            float4 af1 = *(float4*)&As[kk * 132 + ty * 8 + 4];
            float4 bf0 = *(float4*)&Bs[kk * 132 + tx * 8];
            float4 bf1 = *(float4*)&Bs[kk * 132 + tx * 8 + 4];
            ull a2[4] = {pk2(af0.x, af0.y), pk2(af0.z, af0.w),
                         pk2(af1.x, af1.y), pk2(af1.z, af1.w)};
            ull b2[8] = {pk2(bf0.x, bf0.x), pk2(bf0.y, bf0.y),
                         pk2(bf0.z, bf0.z), pk2(bf0.w, bf0.w),
                         pk2(bf1.x, bf1.x), pk2(bf1.y, bf1.y),
                         pk2(bf1.z, bf1.z), pk2(bf1.w, bf1.w)};
            #pragma unroll
            for (int i = 0; i < 4; i++)
                #pragma unroll
                for (int j = 0; j < 8; j++)
                    acc2[i][j] = ffma2(a2[i], b2[j], acc2[i][j]);
        }
    }

    // epilogue
    float4 bb0 = *(const float4*)(bias + bn + tx * 8);
    float4 bb1 = *(const float4*)(bias + bn + tx * 8 + 4);
    const float bias8[8] = {bb0.x, bb0.y, bb0.z, bb0.w,
                            bb1.x, bb1.y, bb1.z, bb1.w};
    const int b    = bm >> 12;
    const int s0   = bm & (SS - 1);
    const int head = (bn >> 6) + (tx >> 3);
    const int d0   = (tx * 8) & 63;
    float* dbase = dst + ((size_t)(b * NH + head) * SS) * HD + d0;
    #pragma unroll
    for (int p = 0; p < 4; p++) {
        float lo[8], hi[8];
        #pragma unroll
        for (int j = 0; j < 8; j++) upk2(lo[j], hi[j], acc2[p][j]);
        int s = s0 + ty * 8 + p * 2;
        float4 o0a, o0b, o1a, o1b;
        o0a.x = (lo[0]+bias8[0])*scale; o0a.y = (lo[1]+bias8[1])*scale;
        o0a.z = (lo[2]+bias8[2])*scale; o0a.w = (lo[3]+bias8[3])*scale;
        o0b.x = (lo[4]+bias8[4])*scale; o0b.y = (lo[5]+bias8[5])*scale;
        o0b.z = (lo[6]+bias8[6])*scale; o0b.w = (lo[7]+bias8[7])*scale;
        o1a.x = (hi[0]+bias8[0])*scale; o1a.y = (hi[1]+bias8[1])*scale;
        o1a.z = (hi[2]+bias8[2])*scale; o1a.w = (hi[3]+bias8[3])*scale;
        o1b.x = (hi[4]+bias8[4])*scale; o1b.y = (hi[5]+bias8[5])*scale;
        o1b.z = (hi[6]+bias8[6])*scale; o1b.w = (hi[7]+bias8[7])*scale;
        *(float4*)(dbase + (size_t)s * HD)           = o0a;
        *(float4*)(dbase + (size_t)s * HD + 4)       = o0b;
        *(float4*)(dbase + (size_t)(s + 1) * HD)     = o1a;
        *(float4*)(dbase + (size_t)(s + 1) * HD + 4) = o1b;
    }
}

// ---------------------------------------------------------------------------
// Banded flash attention: 128-query tile, 10 key tiles of 64, 8x4 microtiles,
// f32x2 matmuls, single-pass softmax (poly exp), register row sums.
// ---------------------------------------------------------------------------
#define QT_STRD 132
#define KV_STRD 68
#define SM_QT   0
#define SM_KT   (64 * QT_STRD)
#define SM_VS   (SM_KT + 64 * KV_STRD)
#define SM_P    (SM_VS + 64 * KV_STRD)
#define SM_FMK  (SM_P + 128 * KV_STRD)
#define SMEM_FLOATS (SM_FMK + 64)

__global__ __launch_bounds__(256, 2) void attn_kernel(
    const float* __restrict__ q, const float* __restrict__ k,
    const float* __restrict__ v, const float* __restrict__ fmask,
    const unsigned char* __restrict__ imask, float* __restrict__ out)
{
    extern __shared__ float smf[];
    float* Qt  = smf + SM_QT;            // [d][r] 64 x 132
    float* Kt  = smf + SM_KT;            // [d][c] 64 x 68
    float* Vs  = smf + SM_VS;            // [key][d] 64 x 68
    float* P   = smf + SM_P;             // [r][c] 128 x 68
    float* fmk = smf + SM_FMK;           // 64

    const int tid = threadIdx.x;
    const int bh  = blockIdx.y;
    const int b   = bh / NH;
    const int hh  = bh % NH;
    const int q0  = blockIdx.x * 128;

    const float* qb = q + (size_t)bh * SS * HD;
    const float* kb = k + (size_t)bh * SS * HD;
    const float* vb = v + (size_t)bh * SS * HD;

    const int ty = tid >> 4, tx = tid & 15;

    // load Q transposed: 128 rows x 64 d
    {
        const int rr0 = tid >> 4;
        const int d4  = (tid & 15) << 2;
        #pragma unroll
        for (int it = 0; it < 8; it++) {
            int rr = rr0 + it * 16;
            float4 t = *(const float4*)(qb + (size_t)(q0 + rr) * HD + d4);
            Qt[(d4 + 0) * QT_STRD + rr] = t.x;
            Qt[(d4 + 1) * QT_STRD + rr] = t.y;
            Qt[(d4 + 2) * QT_STRD + rr] = t.z;
            Qt[(d4 + 3) * QT_STRD + rr] = t.w;
        }
    }

    ull acc2[8][2];                      // 8 rows x 4 d (col pairs)
    #pragma unroll
    for (int i = 0; i < 8; i++) { acc2[i][0] = 0ull; acc2[i][1] = 0ull; }
    float rsum[8];
    #pragma unroll
    for (int i = 0; i < 8; i++) rsum[i] = 0.f;

    __syncthreads();

    for (int t = 0; t < 10; t++) {
        const int kstart = q0 - WIN + t * 64;
        if (kstart + 63 < 0 || kstart >= SS) continue;
        const bool edge = !(t >= 2 && t <= 7 && kstart >= 0 &&
                            kstart + 63 < SS);

        // load K transposed, V natural, fmask slice
        {
            const int rr0 = tid >> 4;
            const int d4  = (tid & 15) << 2;
            #pragma unroll
            for (int it = 0; it < 4; it++) {
                int rr = rr0 + it * 16;
                int kg = kstart + rr;
                float4 kv = make_float4(0.f, 0.f, 0.f, 0.f);
                float4 vv = make_float4(0.f, 0.f, 0.f, 0.f);
                if (kg >= 0 && kg < SS) {
                    kv = *(const float4*)(kb + (size_t)kg * HD + d4);
                    vv = *(const float4*)(vb + (size_t)kg * HD + d4);
                }
                Kt[(d4 + 0) * KV_STRD + rr] = kv.x;
                Kt[(d4 + 1) * KV_STRD + rr] = kv.y;
                Kt[(d4 + 2) * KV_STRD + rr] = kv.z;
                Kt[(d4 + 3) * KV_STRD + rr] = kv.w;
                *(float4*)&Vs[rr * KV_STRD + d4] = vv;
            }
            if (tid < 64) {
                int kg = kstart + tid;
                float mv = (kg >= 0 && kg < SS) ? fmask[b * SS + kg] : 0.f;
                fmk[tid] = (mv != 0.f) ? -1e30f : 0.f;
            }
        }
        __syncthreads();

        // S = Q K^T: 8 rows x 4 cols per thread
        ull s2[4][4];                    // 4 row-pairs x 4 cols
        #pragma unroll
        for (int i = 0; i < 4; i++)
            #pragma unroll
            for (int j = 0; j < 4; j++) s2[i][j] = 0ull;
        #pragma unroll 8
        for (int kk = 0; kk < 64; kk++) {
            float4 qf0 = *(float4*)&Qt[kk * QT_STRD + ty * 8];
            float4 qf1 = *(float4*)&Qt[kk * QT_STRD + ty * 8 + 4];
            float4 kf  = *(float4*)&Kt[kk * KV_STRD + tx * 4];
            ull q2[4] = {pk2(qf0.x, qf0.y), pk2(qf0.z, qf0.w),
                         pk2(qf1.x, qf1.y), pk2(qf1.z, qf1.w)};
            ull k2[4] = {pk2(kf.x, kf.x), pk2(kf.y, kf.y),
                         pk2(kf.z, kf.z), pk2(kf.w, kf.w)};
            #pragma unroll
            for (int i = 0; i < 4; i++)
                #pragma unroll
                for (int j = 0; j < 4; j++)
                    s2[i][j] = ffma2(q2[i], k2[j], s2[i][j]);
        }

        // exp + masked write to P + register row sums
        {
            float sv[8][4];
            #pragma unroll
            for (int ip = 0; ip < 4; ip++)
                #pragma unroll
                for (int j = 0; j < 4; j++)
                    upk2(sv[2*ip][j], sv[2*ip+1][j], s2[ip][j]);
            float4 fmv = *(float4*)&fmk[tx * 4];
            const float fm[4] = {fmv.x, fmv.y, fmv.z, fmv.w};
            #pragma unroll
            for (int i = 0; i < 8; i++) {
                float4 prow;
                float part;
                if (!edge) {
                    float p0 = expfast(sv[i][0] + fm[0]);
                    float p1 = expfast(sv[i][1] + fm[1]);
                    float p2 = expfast(sv[i][2] + fm[2]);
                    float p3 = expfast(sv[i][3] + fm[3]);
                    prow = make_float4(p0, p1, p2, p3);
                    part = (p0 + p1) + (p2 + p3);
                } else {
                    int rg = q0 + ty * 8 + i;
                    part = 0.f;
                    float pv[4];
                    #pragma unroll
                    for (int j = 0; j < 4; j++) {
                        int kg = kstart + tx * 4 + j;
                        bool valid = (kg >= 0) && (kg < SS) &&
                                     (kg >= rg - WIN) && (kg <= rg + WIN);
                        float p = valid ? expfast(sv[i][j] + fm[j]) : 0.f;
                        pv[j] = p;
                        part += p;
                    }
                    prow = make_float4(pv[0], pv[1], pv[2], pv[3]);
                }
                *(float4*)&P[(ty * 8 + i) * KV_STRD + tx * 4] = prow;
                part += __shfl_xor_sync(0xffffffffu, part, 1);
                part += __shfl_xor_sync(0xffffffffu, part, 2);
                part += __shfl_xor_sync(0xffffffffu, part, 4);
                part += __shfl_xor_sync(0xffffffffu, part, 8);
                rsum[i] += part;
            }
        }
        __syncthreads();

        // acc += P @ V: 8 rows x 4 d per thread
        {
            #pragma unroll 4
            for (int k4 = 0; k4 < 16; k4++) {
                float4 pr[8];
                #pragma unroll
                for (int i = 0; i < 8; i++)
                    pr[i] = *(float4*)&P[(ty * 8 + i) * KV_STRD + k4 * 4];
                #pragma unroll
                for (int u = 0; u < 4; u++) {
                    float4 vf = *(float4*)&Vs[(k4 * 4 + u) * KV_STRD + tx * 4];
                    ull v2[2] = {pk2(vf.x, vf.y), pk2(vf.z, vf.w)};
                    const float pu[8] = {
                        u==0?pr[0].x:u==1?pr[0].y:u==2?pr[0].z:pr[0].w,
                        u==0?pr[1].x:u==1?pr[1].y:u==2?pr[1].z:pr[1].w,
                        u==0?pr[2].x:u==1?pr[2].y:u==2?pr[2].z:pr[2].w,
                        u==0?pr[3].x:u==1?pr[3].y:u==2?pr[3].z:pr[3].w,
                        u==0?pr[4].x:u==1?pr[4].y:u==2?pr[4].z:pr[4].w,
                        u==0?pr[5].x:u==1?pr[5].y:u==2?pr[5].z:pr[5].w,
                        u==0?pr[6].x:u==1?pr[6].y:u==2?pr[6].z:pr[6].w,
                        u==0?pr[7].x:u==1?pr[7].y:u==2?pr[7].z:pr[7].w};
                    #pragma unroll
                    for (int i = 0; i < 8; i++) {
                        ull pd = pk2(pu[i], pu[i]);
                        acc2[i][0] = ffma2(pd, v2[0], acc2[i][0]);
                        acc2[i][1] = ffma2(pd, v2[1], acc2[i][1]);
                    }
                }
            }
        }
        __syncthreads();
    }

    // epilogue: normalize, index-mask, write [B,S,D]
    #pragma unroll
    for (int i = 0; i < 8; i++) {
        int rg = q0 + ty * 8 + i;
        float inv = 1.f / rsum[i];
        bool masked = imask[b * SS + rg] != 0;
        float a0, a1, a2v, a3;
        upk2(a0, a1, acc2[i][0]);
        upk2(a2v, a3, acc2[i][1]);
        float4 o;
        o.x = masked ? 0.f : a0  * inv;
        o.y = masked ? 0.f : a1  * inv;
        o.z = masked ? 0.f : a2v * inv;
        o.w = masked ? 0.f : a3  * inv;
        *(float4*)(out + ((size_t)b * SS + rg) * DD + hh * HD + tx * 4) = o;
    }
}

// ---------------------------------------------------------------------------
extern "C" void kernel_launch(void* const* d_in, const int* in_sizes, int n_in,
                              void* d_out, int out_size)
{
    const float* hidden = (const float*)d_in[0];
    const float* amask  = (const float*)d_in[1];
    const unsigned char* imask = (const unsigned char*)d_in[2];
    const float* Wq = (const float*)d_in[3];
    const float* bq = (const float*)d_in[4];
    const float* Wk = (const float*)d_in[5];
    const float* bk = (const float*)d_in[6];
    const float* Wv = (const float*)d_in[7];
    const float* bv = (const float*)d_in[8];
    float* out = (float*)d_out;

    float *pq, *pk, *pv;
    cudaGetSymbolAddress((void**)&pq, g_q);
    cudaGetSymbolAddress((void**)&pk, g_k);
    cudaGetSymbolAddress((void**)&pv, g_v);

    const size_t smem_bytes = SMEM_FLOATS * sizeof(float);
    cudaFuncSetAttribute(attn_kernel,
                         cudaFuncAttributeMaxDynamicSharedMemorySize,
                         (int)smem_bytes);

    dim3 ggrid(DD / 128, (BB * SS) / 128, 3);
    qkv_gemm3<<<ggrid, 256>>>(hidden, Wq, Wk, Wv, bq, bk, bv, pq, pk, pv);

    dim3 agrid(SS / 128, BB * NH);
    attn_kernel<<<agrid, 256, smem_bytes>>>(pq, pk, pv, amask, imask, out);
}

// round 9
// speedup vs baseline: 1.5440x; 1.5440x over previous
#include <cuda_runtime.h>
#include <cuda_bf16.h>
#include <math.h>
#include <stdint.h>

#define BB 2
#define SS 4096
#define DD 768
#define NH 12
#define HD 64
#define WIN 256

typedef unsigned long long ull;

// scratch
__device__ float g_q[BB*NH*SS*HD];
__device__ float g_k[BB*NH*SS*HD];
__device__ float g_v[BB*NH*SS*HD];
__device__ __nv_bfloat16 g_ahi[BB*SS*DD];
__device__ __nv_bfloat16 g_alo[BB*SS*DD];
__device__ __nv_bfloat16 g_wthi[3][DD*DD];   // [N][K] transposed
__device__ __nv_bfloat16 g_wtlo[3][DD*DD];

// ---------------------------------------------------------------------------
// packed f32x2 helpers (for attention)
// ---------------------------------------------------------------------------
__device__ __forceinline__ ull pk2(float a, float b) {
    ull r;
    asm("mov.b64 %0, {%1,%2};" : "=l"(r) : "f"(a), "f"(b));
    return r;
}
__device__ __forceinline__ void upk2(float& a, float& b, ull v) {
    asm("mov.b64 {%0,%1}, %2;" : "=f"(a), "=f"(b) : "l"(v));
}
__device__ __forceinline__ ull ffma2(ull a, ull b, ull c) {
    ull d;
    asm("fma.rn.f32x2 %0, %1, %2, %3;" : "=l"(d) : "l"(a), "l"(b), "l"(c));
    return d;
}

__device__ __forceinline__ float expfast(float x) {
    float z = x * 1.4426950408889634f;
    z = fmaxf(z, -126.0f);
    float t = z + 12582912.0f;
    int   ni = __float_as_int(t) - 0x4B400000;
    float n = t - 12582912.0f;
    float r = z - n;
    const float c6 = 1.5403530393381609e-4f;
    const float c5 = 1.3333558146428443e-3f;
    const float c4 = 9.6181291076284772e-3f;
    const float c3 = 5.5504108664821580e-2f;
    const float c2 = 2.4022650695910072e-1f;
    const float c1 = 6.9314718055994531e-1f;
    float p = fmaf(c6, r, c5);
    p = fmaf(p, r, c4);
    p = fmaf(p, r, c3);
    p = fmaf(p, r, c2);
    p = fmaf(p, r, c1);
    p = fmaf(p, r, 1.0f);
    float sc = __int_as_float((ni + 127) << 23);
    return p * sc;
}

// ---------------------------------------------------------------------------
// mma.sync / ldmatrix / cp.async helpers (sm_80+ baseline, OK on plain sm_103)
// ---------------------------------------------------------------------------
__device__ __forceinline__ uint32_t smem_u32(const void* p) {
    uint32_t a;
    asm("{ .reg .u64 t; cvta.to.shared.u64 t, %1; cvt.u32.u64 %0, t; }"
        : "=r"(a) : "l"(p));
    return a;
}
#define LDSM4(r0,r1,r2,r3,addr) \
    asm volatile("ldmatrix.sync.aligned.m8n8.x4.shared.b16 {%0,%1,%2,%3}, [%4];" \
        : "=r"(r0),"=r"(r1),"=r"(r2),"=r"(r3) : "r"(addr))
#define MMA16816(c, a, b0, b1) \
    asm volatile("mma.sync.aligned.m16n8k16.row.col.f32.bf16.bf16.f32 " \
        "{%0,%1,%2,%3}, {%4,%5,%6,%7}, {%8,%9}, {%0,%1,%2,%3};" \
        : "+f"((c)[0]),"+f"((c)[1]),"+f"((c)[2]),"+f"((c)[3]) \
        : "r"((a)[0]),"r"((a)[1]),"r"((a)[2]),"r"((a)[3]),"r"(b0),"r"(b1))
__device__ __forceinline__ void cpa16(uint32_t dst, const void* src) {
    asm volatile("cp.async.cg.shared.global [%0], [%1], 16;"
                 :: "r"(dst), "l"(src));
}
#define CPA_COMMIT() asm volatile("cp.async.commit_group;" ::: "memory")
#define CPA_WAIT(n)  asm volatile("cp.async.wait_group %0;" :: "n"(n) : "memory")

// ---------------------------------------------------------------------------
// split hidden -> bf16 hi/lo
// ---------------------------------------------------------------------------
__global__ __launch_bounds__(256) void asplit(const float4* __restrict__ in,
                                              __nv_bfloat162* __restrict__ hi,
                                              __nv_bfloat162* __restrict__ lo,
                                              int n4)
{
    int i = blockIdx.x * blockDim.x + threadIdx.x;
    int stride = gridDim.x * blockDim.x;
    for (; i < n4; i += stride) {
        float4 f = in[i];
        __nv_bfloat16 hx = __float2bfloat16(f.x);
        __nv_bfloat16 hy = __float2bfloat16(f.y);
        __nv_bfloat16 hz = __float2bfloat16(f.z);
        __nv_bfloat16 hw = __float2bfloat16(f.w);
        hi[2*i]   = __nv_bfloat162(hx, hy);
        hi[2*i+1] = __nv_bfloat162(hz, hw);
        lo[2*i]   = __nv_bfloat162(__float2bfloat16(f.x - __bfloat162float(hx)),
                                   __float2bfloat16(f.y - __bfloat162float(hy)));
        lo[2*i+1] = __nv_bfloat162(__float2bfloat16(f.z - __bfloat162float(hz)),
                                   __float2bfloat16(f.w - __bfloat162float(hw)));
    }
}

// transpose + split W [K,N] fp32 -> Wt hi/lo [N,K] bf16
__global__ __launch_bounds__(256) void wsplit(const float* __restrict__ W,
                                              __nv_bfloat16* __restrict__ hi,
                                              __nv_bfloat16* __restrict__ lo)
{
    __shared__ float t[32][33];
    int tx = threadIdx.x, ty = threadIdx.y;
    int bx = blockIdx.x * 32, by = blockIdx.y * 32;
    #pragma unroll
    for (int i = 0; i < 4; i++)
        t[ty + i*8][tx] = W[(size_t)(by + ty + i*8) * DD + bx + tx];
    __syncthreads();
    #pragma unroll
    for (int i = 0; i < 4; i++) {
        float x = t[tx][ty + i*8];
        __nv_bfloat16 h = __float2bfloat16(x);
        hi[(size_t)(bx + ty + i*8) * DD + by + tx] = h;
        lo[(size_t)(bx + ty + i*8) * DD + by + tx] =
            __float2bfloat16(x - __bfloat162float(h));
    }
}

// ---------------------------------------------------------------------------
// QKV GEMM on tensor cores: 128x128 tile, 8 warps (32x64 each), K-chunk 32,
// cp.async double buffer, 3-pass bf16 hi/lo split (fp32-class accuracy).
// ---------------------------------------------------------------------------
#define TSTR    40                       // smem row stride (bf16), conflict-free
#define TILE_E  (128 * TSTR)             // 5120 bf16 per tile
#define STAGE_E (4 * TILE_E)             // Ahi, Alo, Whi, Wlo
#define G_SMEM  (2 * STAGE_E * 2)        // 81920 B
#define NCHUNK  (DD / 32)                // 24

__global__ __launch_bounds__(256) void qkv_gemm_mma(
    const __nv_bfloat16* __restrict__ Ahi, const __nv_bfloat16* __restrict__ Alo,
    const __nv_bfloat16* __restrict__ Whi_all,
    const __nv_bfloat16* __restrict__ Wlo_all,
    const float* __restrict__ bq, const float* __restrict__ bk,
    const float* __restrict__ bv,
    float* __restrict__ dq, float* __restrict__ dk, float* __restrict__ dv)
{
    extern __shared__ __nv_bfloat16 gsm[];
    const uint32_t smb = smem_u32(gsm);

    const int z = blockIdx.z;
    const __nv_bfloat16* __restrict__ Whi = Whi_all + (size_t)z * DD * DD;
    const __nv_bfloat16* __restrict__ Wlo = Wlo_all + (size_t)z * DD * DD;
    const float* __restrict__ bias = (z == 0) ? bq : ((z == 1) ? bk : bv);
    float* __restrict__ dst        = (z == 0) ? dq : ((z == 1) ? dk : dv);
    const float scale              = (z == 0) ? 0.125f : 1.0f;

    const int tid  = threadIdx.x;
    const int wid  = tid >> 5;
    const int lane = tid & 31;
    const int bm   = blockIdx.y * 128;
    const int bn   = blockIdx.x * 128;
    const int mrow0 = (wid & 3) * 32;
    const int ncol0 = (wid >> 2) * 64;

    // loader indices: 512 uint4 per tile, 2 per thread per tile
    const int lr0 = tid >> 2;                // row for it=0 (0..63)
    const int lg  = tid & 3;                 // 16B group (0..3)

    float acc[2][8][4];
    #pragma unroll
    for (int i = 0; i < 2; i++)
        #pragma unroll
        for (int j = 0; j < 8; j++)
            #pragma unroll
            for (int u = 0; u < 4; u++) acc[i][j][u] = 0.f;

    // ldmatrix lane addressing
    const int lm  = lane >> 3;               // matrix index 0..3
    const int lr8 = lane & 7;
    // A frag: row = mt + (lm&1)*8 + lr8 ; col = kk + (lm>>1)*8
    const int a_row_off = (lm & 1) * 8 + lr8;
    const int a_col_off = (lm >> 1) * 8;
    // B frag: nrow = ng*16 + (lm>>1)*8 + lr8 ; col = kk + (lm&1)*8
    const int b_row_off = (lm >> 1) * 8 + lr8;
    const int b_col_off = (lm & 1) * 8;

    // issue loads for a chunk into stage s
    auto load_chunk = [&](int c, int s) {
        const int k0 = c * 32;
        const uint32_t sbase = smb + (uint32_t)(s * STAGE_E) * 2;
        const __nv_bfloat16* srcs[4] = {
            Ahi + (size_t)bm * DD + k0, Alo + (size_t)bm * DD + k0,
            Whi + (size_t)bn * DD + k0, Wlo + (size_t)bn * DD + k0 };
        #pragma unroll
        for (int t4 = 0; t4 < 4; t4++) {
            #pragma unroll
            for (int it = 0; it < 2; it++) {
                int r = lr0 + it * 64;
                cpa16(sbase + (uint32_t)(t4 * TILE_E + r * TSTR + lg * 8) * 2,
                      srcs[t4] + (size_t)r * DD + lg * 8);
            }
        }
        CPA_COMMIT();
    };

    load_chunk(0, 0);
    CPA_WAIT(0);
    __syncthreads();

    for (int c = 0; c < NCHUNK; c++) {
        if (c + 1 < NCHUNK) {
            load_chunk(c + 1, (c + 1) & 1);
            CPA_WAIT(1);
        } else {
            CPA_WAIT(0);
        }
        __syncthreads();

        const uint32_t sbase = smb + (uint32_t)((c & 1) * STAGE_E) * 2;
        const uint32_t baseAhi = sbase;
        const uint32_t baseAlo = sbase + (uint32_t)TILE_E * 2;
        const uint32_t baseWhi = sbase + (uint32_t)(2 * TILE_E) * 2;
        const uint32_t baseWlo = sbase + (uint32_t)(3 * TILE_E) * 2;

        #pragma unroll
        for (int kk = 0; kk < 32; kk += 16) {
            uint32_t ah[2][4], al[2][4];
            #pragma unroll
            for (int mt2 = 0; mt2 < 2; mt2++) {
                uint32_t off = (uint32_t)((mrow0 + mt2 * 16 + a_row_off) * TSTR
                                          + kk + a_col_off) * 2;
                LDSM4(ah[mt2][0], ah[mt2][1], ah[mt2][2], ah[mt2][3],
                      baseAhi + off);
                LDSM4(al[mt2][0], al[mt2][1], al[mt2][2], al[mt2][3],
                      baseAlo + off);
            }
            uint32_t bh[16], bl[16];
            #pragma unroll
            for (int ng = 0; ng < 4; ng++) {
                uint32_t off = (uint32_t)((ncol0 + ng * 16 + b_row_off) * TSTR
                                          + kk + b_col_off) * 2;
                LDSM4(bh[ng*4+0], bh[ng*4+1], bh[ng*4+2], bh[ng*4+3],
                      baseWhi + off);
                LDSM4(bl[ng*4+0], bl[ng*4+1], bl[ng*4+2], bl[ng*4+3],
                      baseWlo + off);
            }
            #pragma unroll
            for (int mt2 = 0; mt2 < 2; mt2++) {
                #pragma unroll
                for (int nt = 0; nt < 8; nt++) {
                    // bh layout: frag nt -> regs [ (nt>>1)*4 + (nt&1)*2 , +1 ]
                    int bi = (nt >> 1) * 4 + (nt & 1) * 2;
                    MMA16816(acc[mt2][nt], ah[mt2], bh[bi], bh[bi+1]);
                    MMA16816(acc[mt2][nt], ah[mt2], bl[bi], bl[bi+1]);
                    MMA16816(acc[mt2][nt], al[mt2], bh[bi], bh[bi+1]);
                }
            }
        }
        __syncthreads();
    }

    // epilogue: bias + scale, write to [B,H,S,HD]
    #pragma unroll
    for (int mt2 = 0; mt2 < 2; mt2++) {
        int grow0 = bm + mrow0 + mt2 * 16 + (lane >> 2);
        int b0 = grow0 >> 12;
        int s0 = grow0 & (SS - 1);
        #pragma unroll
        for (int nt = 0; nt < 8; nt++) {
            int gcol = bn + ncol0 + nt * 8 + 2 * (lane & 3);
            int head = gcol >> 6;
            int d    = gcol & 63;
            float2 bsv = *(const float2*)(bias + gcol);
            float* p = dst + ((size_t)(b0 * NH + head) * SS + s0) * HD + d;
            float2 o0, o1;
            o0.x = (acc[mt2][nt][0] + bsv.x) * scale;
            o0.y = (acc[mt2][nt][1] + bsv.y) * scale;
            o1.x = (acc[mt2][nt][2] + bsv.x) * scale;
            o1.y = (acc[mt2][nt][3] + bsv.y) * scale;
            *(float2*)p = o0;
            *(float2*)(p + (size_t)8 * HD) = o1;
        }
    }
}

// ---------------------------------------------------------------------------
// Banded flash attention (R8, unchanged): 128-q tile, 10 key tiles, f32x2.
// ---------------------------------------------------------------------------
#define QT_STRD 132
#define KV_STRD 68
#define SM_QT   0
#define SM_KT   (64 * QT_STRD)
#define SM_VS   (SM_KT + 64 * KV_STRD)
#define SM_P    (SM_VS + 64 * KV_STRD)
#define SM_FMK  (SM_P + 128 * KV_STRD)
#define SMEM_FLOATS (SM_FMK + 64)

__global__ __launch_bounds__(256, 2) void attn_kernel(
    const float* __restrict__ q, const float* __restrict__ k,
    const float* __restrict__ v, const float* __restrict__ fmask,
    const unsigned char* __restrict__ imask, float* __restrict__ out)
{
    extern __shared__ float smf[];
    float* Qt  = smf + SM_QT;
    float* Kt  = smf + SM_KT;
    float* Vs  = smf + SM_VS;
    float* P   = smf + SM_P;
    float* fmk = smf + SM_FMK;

    const int tid = threadIdx.x;
    const int bh  = blockIdx.y;
    const int b   = bh / NH;
    const int hh  = bh % NH;
    const int q0  = blockIdx.x * 128;

    const float* qb = q + (size_t)bh * SS * HD;
    const float* kb = k + (size_t)bh * SS * HD;
    const float* vb = v + (size_t)bh * SS * HD;

    const int ty = tid >> 4, tx = tid & 15;

    {
        const int rr0 = tid >> 4;
        const int d4  = (tid & 15) << 2;
        #pragma unroll
        for (int it = 0; it < 8; it++) {
            int rr = rr0 + it * 16;
            float4 t = *(const float4*)(qb + (size_t)(q0 + rr) * HD + d4);
            Qt[(d4 + 0) * QT_STRD + rr] = t.x;
            Qt[(d4 + 1) * QT_STRD + rr] = t.y;
            Qt[(d4 + 2) * QT_STRD + rr] = t.z;
            Qt[(d4 + 3) * QT_STRD + rr] = t.w;
        }
    }

    ull acc2[8][2];
    #pragma unroll
    for (int i = 0; i < 8; i++) { acc2[i][0] = 0ull; acc2[i][1] = 0ull; }
    float rsum[8];
    #pragma unroll
    for (int i = 0; i < 8; i++) rsum[i] = 0.f;

    __syncthreads();

    for (int t = 0; t < 10; t++) {
        const int kstart = q0 - WIN + t * 64;
        if (kstart + 63 < 0 || kstart >= SS) continue;
        const bool edge = !(t >= 2 && t <= 7 && kstart >= 0 &&
                            kstart + 63 < SS);

        {
            const int rr0 = tid >> 4;
            const int d4  = (tid & 15) << 2;
            #pragma unroll
            for (int it = 0; it < 4; it++) {
                int rr = rr0 + it * 16;
                int kg = kstart + rr;
                float4 kv = make_float4(0.f, 0.f, 0.f, 0.f);
                float4 vv = make_float4(0.f, 0.f, 0.f, 0.f);
                if (kg >= 0 && kg < SS) {
                    kv = *(const float4*)(kb + (size_t)kg * HD + d4);
                    vv = *(const float4*)(vb + (size_t)kg * HD + d4);
                }
                Kt[(d4 + 0) * KV_STRD + rr] = kv.x;
                Kt[(d4 + 1) * KV_STRD + rr] = kv.y;
                Kt[(d4 + 2) * KV_STRD + rr] = kv.z;
                Kt[(d4 + 3) * KV_STRD + rr] = kv.w;
                *(float4*)&Vs[rr * KV_STRD + d4] = vv;
            }
            if (tid < 64) {
                int kg = kstart + tid;
                float mv = (kg >= 0 && kg < SS) ? fmask[b * SS + kg] : 0.f;
                fmk[tid] = (mv != 0.f) ? -1e30f : 0.f;
            }
        }
        __syncthreads();

        ull s2[4][4];
        #pragma unroll
        for (int i = 0; i < 4; i++)
            #pragma unroll
            for (int j = 0; j < 4; j++) s2[i][j] = 0ull;
        #pragma unroll 8
        for (int kk = 0; kk < 64; kk++) {
            float4 qf0 = *(float4*)&Qt[kk * QT_STRD + ty * 8];
            float4 qf1 = *(float4*)&Qt[kk * QT_STRD + ty * 8 + 4];
            float4 kf  = *(float4*)&Kt[kk * KV_STRD + tx * 4];
            ull q2[4] = {pk2(qf0.x, qf0.y), pk2(qf0.z, qf0.w),
                         pk2(qf1.x, qf1.y), pk2(qf1.z, qf1.w)};
            ull k2[4] = {pk2(kf.x, kf.x), pk2(kf.y, kf.y),
                         pk2(kf.z, kf.z), pk2(kf.w, kf.w)};
            #pragma unroll
            for (int i = 0; i < 4; i++)
                #pragma unroll
                for (int j = 0; j < 4; j++)
                    s2[i][j] = ffma2(q2[i], k2[j], s2[i][j]);
        }

        {
            float sv[8][4];
            #pragma unroll
            for (int ip = 0; ip < 4; ip++)
                #pragma unroll
                for (int j = 0; j < 4; j++)
                    upk2(sv[2*ip][j], sv[2*ip+1][j], s2[ip][j]);
            float4 fmv = *(float4*)&fmk[tx * 4];
            const float fm[4] = {fmv.x, fmv.y, fmv.z, fmv.w};
            #pragma unroll
            for (int i = 0; i < 8; i++) {
                float4 prow;
                float part;
                if (!edge) {
                    float p0 = expfast(sv[i][0] + fm[0]);
                    float p1 = expfast(sv[i][1] + fm[1]);
                    float p2 = expfast(sv[i][2] + fm[2]);
                    float p3 = expfast(sv[i][3] + fm[3]);
                    prow = make_float4(p0, p1, p2, p3);
                    part = (p0 + p1) + (p2 + p3);
                } else {
                    int rg = q0 + ty * 8 + i;
                    part = 0.f;
                    float pv[4];
                    #pragma unroll
                    for (int j = 0; j < 4; j++) {
                        int kg = kstart + tx * 4 + j;
                        bool valid = (kg >= 0) && (kg < SS) &&
                                     (kg >= rg - WIN) && (kg <= rg + WIN);
                        float p = valid ? expfast(sv[i][j] + fm[j]) : 0.f;
                        pv[j] = p;
                        part += p;
                    }
                    prow = make_float4(pv[0], pv[1], pv[2], pv[3]);
                }
                *(float4*)&P[(ty * 8 + i) * KV_STRD + tx * 4] = prow;
                part += __shfl_xor_sync(0xffffffffu, part, 1);
                part += __shfl_xor_sync(0xffffffffu, part, 2);
                part += __shfl_xor_sync(0xffffffffu, part, 4);
                part += __shfl_xor_sync(0xffffffffu, part, 8);
                rsum[i] += part;
            }
        }
        __syncthreads();

        {
            #pragma unroll 4
            for (int k4 = 0; k4 < 16; k4++) {
                float4 pr[8];
                #pragma unroll
                for (int i = 0; i < 8; i++)
                    pr[i] = *(float4*)&P[(ty * 8 + i) * KV_STRD + k4 * 4];
                #pragma unroll
                for (int u = 0; u < 4; u++) {
                    float4 vf = *(float4*)&Vs[(k4 * 4 + u) * KV_STRD + tx * 4];
                    ull v2[2] = {pk2(vf.x, vf.y), pk2(vf.z, vf.w)};
                    const float pu[8] = {
                        u==0?pr[0].x:u==1?pr[0].y:u==2?pr[0].z:pr[0].w,
                        u==0?pr[1].x:u==1?pr[1].y:u==2?pr[1].z:pr[1].w,
                        u==0?pr[2].x:u==1?pr[2].y:u==2?pr[2].z:pr[2].w,
                        u==0?pr[3].x:u==1?pr[3].y:u==2?pr[3].z:pr[3].w,
                        u==0?pr[4].x:u==1?pr[4].y:u==2?pr[4].z:pr[4].w,
                        u==0?pr[5].x:u==1?pr[5].y:u==2?pr[5].z:pr[5].w,
                        u==0?pr[6].x:u==1?pr[6].y:u==2?pr[6].z:pr[6].w,
                        u==0?pr[7].x:u==1?pr[7].y:u==2?pr[7].z:pr[7].w};
                    #pragma unroll
                    for (int i = 0; i < 8; i++) {
                        ull pd = pk2(pu[i], pu[i]);
                        acc2[i][0] = ffma2(pd, v2[0], acc2[i][0]);
                        acc2[i][1] = ffma2(pd, v2[1], acc2[i][1]);
                    }
                }
            }
        }
        __syncthreads();
    }

    #pragma unroll
    for (int i = 0; i < 8; i++) {
        int rg = q0 + ty * 8 + i;
        float inv = 1.f / rsum[i];
        bool masked = imask[b * SS + rg] != 0;
        float a0, a1, a2v, a3;
        upk2(a0, a1, acc2[i][0]);
        upk2(a2v, a3, acc2[i][1]);
        float4 o;
        o.x = masked ? 0.f : a0  * inv;
        o.y = masked ? 0.f : a1  * inv;
        o.z = masked ? 0.f : a2v * inv;
        o.w = masked ? 0.f : a3  * inv;
        *(float4*)(out + ((size_t)b * SS + rg) * DD + hh * HD + tx * 4) = o;
    }
}

// ---------------------------------------------------------------------------
extern "C" void kernel_launch(void* const* d_in, const int* in_sizes, int n_in,
                              void* d_out, int out_size)
{
    const float* hidden = (const float*)d_in[0];
    const float* amask  = (const float*)d_in[1];
    const unsigned char* imask = (const unsigned char*)d_in[2];
    const float* Wq = (const float*)d_in[3];
    const float* bq = (const float*)d_in[4];
    const float* Wk = (const float*)d_in[5];
    const float* bk = (const float*)d_in[6];
    const float* Wv = (const float*)d_in[7];
    const float* bv = (const float*)d_in[8];
    float* out = (float*)d_out;

    float *pq, *pk, *pv;
    __nv_bfloat16 *pahi, *palo, *pwhi, *pwlo;
    cudaGetSymbolAddress((void**)&pq, g_q);
    cudaGetSymbolAddress((void**)&pk, g_k);
    cudaGetSymbolAddress((void**)&pv, g_v);
    cudaGetSymbolAddress((void**)&pahi, g_ahi);
    cudaGetSymbolAddress((void**)&palo, g_alo);
    cudaGetSymbolAddress((void**)&pwhi, g_wthi);
    cudaGetSymbolAddress((void**)&pwlo, g_wtlo);

    const size_t a_smem = SMEM_FLOATS * sizeof(float);
    cudaFuncSetAttribute(attn_kernel,
                         cudaFuncAttributeMaxDynamicSharedMemorySize,
                         (int)a_smem);
    cudaFuncSetAttribute(qkv_gemm_mma,
                         cudaFuncAttributeMaxDynamicSharedMemorySize, G_SMEM);

    // prep: bf16 hi/lo splits
    asplit<<<592, 256>>>((const float4*)hidden,
                         (__nv_bfloat162*)pahi, (__nv_bfloat162*)palo,
                         BB * SS * DD / 4);
    dim3 wb(32, 8), wg(DD / 32, DD / 32);
    wsplit<<<wg, wb>>>(Wq, pwhi + 0 * DD * DD, pwlo + 0 * DD * DD);
    wsplit<<<wg, wb>>>(Wk, pwhi + 1 * DD * DD, pwlo + 1 * DD * DD);
    wsplit<<<wg, wb>>>(Wv, pwhi + 2 * DD * DD, pwlo + 2 * DD * DD);

    // tensor-core QKV GEMMs
    dim3 gg(DD / 128, (BB * SS) / 128, 3);
    qkv_gemm_mma<<<gg, 256, G_SMEM>>>(pahi, palo, pwhi, pwlo,
                                      bq, bk, bv, pq, pk, pv);

    // banded attention
    dim3 agrid(SS / 128, BB * NH);
    attn_kernel<<<agrid, 256, a_smem>>>(pq, pk, pv, amask, imask, out);
}

// round 10
// speedup vs baseline: 2.2869x; 1.4812x over previous
#include <cuda_runtime.h>
#include <cuda_bf16.h>
#include <math.h>
#include <stdint.h>

#define BB 2
#define SS 4096
#define DD 768
#define NH 12
#define HD 64
#define WIN 256
#define BH (BB*NH)

typedef unsigned long long ull;

// ---------------------------------------------------------------------------
// scratch (bf16 hi/lo everywhere)
// ---------------------------------------------------------------------------
__device__ __nv_bfloat16 g_ahi[BB*SS*DD];
__device__ __nv_bfloat16 g_alo[BB*SS*DD];
__device__ __nv_bfloat16 g_wthi[3][DD*DD];
__device__ __nv_bfloat16 g_wtlo[3][DD*DD];
__device__ __nv_bfloat16 g_qhi[BH*SS*HD], g_qlo[BH*SS*HD];
__device__ __nv_bfloat16 g_khi[BH*SS*HD], g_klo[BH*SS*HD];
__device__ __nv_bfloat16 g_vhi[BH*SS*HD], g_vlo[BH*SS*HD];
__device__ __nv_bfloat16 g_vthi[BH*HD*SS], g_vtlo[BH*HD*SS];

// ---------------------------------------------------------------------------
// helpers
// ---------------------------------------------------------------------------
__device__ __forceinline__ uint32_t smem_u32(const void* p) {
    uint32_t a;
    asm("{ .reg .u64 t; cvta.to.shared.u64 t, %1; cvt.u32.u64 %0, t; }"
        : "=r"(a) : "l"(p));
    return a;
}
#define LDSM4(r0,r1,r2,r3,addr) \
    asm volatile("ldmatrix.sync.aligned.m8n8.x4.shared.b16 {%0,%1,%2,%3}, [%4];" \
        : "=r"(r0),"=r"(r1),"=r"(r2),"=r"(r3) : "r"(addr))
#define MMA16816(c, a, b0, b1) \
    asm volatile("mma.sync.aligned.m16n8k16.row.col.f32.bf16.bf16.f32 " \
        "{%0,%1,%2,%3}, {%4,%5,%6,%7}, {%8,%9}, {%0,%1,%2,%3};" \
        : "+f"((c)[0]),"+f"((c)[1]),"+f"((c)[2]),"+f"((c)[3]) \
        : "r"((a)[0]),"r"((a)[1]),"r"((a)[2]),"r"((a)[3]),"r"(b0),"r"(b1))
__device__ __forceinline__ void cpa16(uint32_t dst, const void* src) {
    asm volatile("cp.async.cg.shared.global [%0], [%1], 16;"
                 :: "r"(dst), "l"(src));
}
#define CPA_COMMIT() asm volatile("cp.async.commit_group;" ::: "memory")
#define CPA_WAIT(n)  asm volatile("cp.async.wait_group %0;" :: "n"(n) : "memory")

// pack two f32 -> bf16x2 (hi half = first operand)
__device__ __forceinline__ uint32_t cvt_bf2(float hi, float lo) {
    uint32_t r;
    asm("cvt.rn.bf16x2.f32 %0, %1, %2;" : "=r"(r) : "f"(hi), "f"(lo));
    return r;
}
__device__ __forceinline__ float bf2_lo(uint32_t u) {
    return __uint_as_float(u << 16);
}
__device__ __forceinline__ float bf2_hi(uint32_t u) {
    return __uint_as_float(u & 0xFFFF0000u);
}

__device__ __forceinline__ float expfast(float x) {
    float z = x * 1.4426950408889634f;
    z = fmaxf(z, -126.0f);
    float t = z + 12582912.0f;
    int   ni = __float_as_int(t) - 0x4B400000;
    float n = t - 12582912.0f;
    float r = z - n;
    float p = fmaf(1.5403530393381609e-4f, r, 1.3333558146428443e-3f);
    p = fmaf(p, r, 9.6181291076284772e-3f);
    p = fmaf(p, r, 5.5504108664821580e-2f);
    p = fmaf(p, r, 2.4022650695910072e-1f);
    p = fmaf(p, r, 6.9314718055994531e-1f);
    p = fmaf(p, r, 1.0f);
    return p * __int_as_float((ni + 127) << 23);
}

// ---------------------------------------------------------------------------
// prep: split hidden / weights into bf16 hi/lo
// ---------------------------------------------------------------------------
__global__ __launch_bounds__(256) void asplit(const float4* __restrict__ in,
                                              __nv_bfloat162* __restrict__ hi,
                                              __nv_bfloat162* __restrict__ lo,
                                              int n4)
{
    int i = blockIdx.x * blockDim.x + threadIdx.x;
    int stride = gridDim.x * blockDim.x;
    for (; i < n4; i += stride) {
        float4 f = in[i];
        __nv_bfloat16 hx = __float2bfloat16(f.x);
        __nv_bfloat16 hy = __float2bfloat16(f.y);
        __nv_bfloat16 hz = __float2bfloat16(f.z);
        __nv_bfloat16 hw = __float2bfloat16(f.w);
        hi[2*i]   = __nv_bfloat162(hx, hy);
        hi[2*i+1] = __nv_bfloat162(hz, hw);
        lo[2*i]   = __nv_bfloat162(__float2bfloat16(f.x - __bfloat162float(hx)),
                                   __float2bfloat16(f.y - __bfloat162float(hy)));
        lo[2*i+1] = __nv_bfloat162(__float2bfloat16(f.z - __bfloat162float(hz)),
                                   __float2bfloat16(f.w - __bfloat162float(hw)));
    }
}

__global__ __launch_bounds__(256) void wsplit(const float* __restrict__ W,
                                              __nv_bfloat16* __restrict__ hi,
                                              __nv_bfloat16* __restrict__ lo)
{
    __shared__ float t[32][33];
    int tx = threadIdx.x, ty = threadIdx.y;
    int bx = blockIdx.x * 32, by = blockIdx.y * 32;
    #pragma unroll
    for (int i = 0; i < 4; i++)
        t[ty + i*8][tx] = W[(size_t)(by + ty + i*8) * DD + bx + tx];
    __syncthreads();
    #pragma unroll
    for (int i = 0; i < 4; i++) {
        float x = t[tx][ty + i*8];
        __nv_bfloat16 h = __float2bfloat16(x);
        hi[(size_t)(bx + ty + i*8) * DD + by + tx] = h;
        lo[(size_t)(bx + ty + i*8) * DD + by + tx] =
            __float2bfloat16(x - __bfloat162float(h));
    }
}

// transpose V [bh][S][64] bf16 -> VT [bh][64][S]; z selects hi/lo
__global__ __launch_bounds__(256) void vtrans(
    const __nv_bfloat16* __restrict__ vhi, const __nv_bfloat16* __restrict__ vlo,
    __nv_bfloat16* __restrict__ vthi, __nv_bfloat16* __restrict__ vtlo)
{
    __shared__ unsigned short sm[64][65];
    const int s0 = blockIdx.x * 64;
    const int bh = blockIdx.y;
    const __nv_bfloat16* src = (blockIdx.z ? vlo : vhi) + (size_t)bh * SS * HD;
    __nv_bfloat16* dst       = (blockIdx.z ? vtlo : vthi) + (size_t)bh * HD * SS;
    const int tid = threadIdx.x;
    const int r = tid >> 2, c0 = (tid & 3) * 16;
    {
        uint4 a = *(const uint4*)(src + (size_t)(s0 + r) * HD + c0);
        uint4 b = *(const uint4*)(src + (size_t)(s0 + r) * HD + c0 + 8);
        const unsigned short* pa = (const unsigned short*)&a;
        const unsigned short* pb = (const unsigned short*)&b;
        #pragma unroll
        for (int i = 0; i < 8; i++) { sm[r][c0+i] = pa[i]; sm[r][c0+8+i] = pb[i]; }
    }
    __syncthreads();
    {
        unsigned short w[16];
        #pragma unroll
        for (int i = 0; i < 16; i++) w[i] = sm[c0 + i][r];
        *(uint4*)(dst + (size_t)r * SS + s0 + c0)     = *(uint4*)&w[0];
        *(uint4*)(dst + (size_t)r * SS + s0 + c0 + 8) = *(uint4*)&w[8];
    }
}

// ---------------------------------------------------------------------------
// QKV GEMM on tensor cores (R9) — epilogue now writes bf16 hi/lo Q/K/V.
// ---------------------------------------------------------------------------
#define TSTR    40
#define TILE_E  (128 * TSTR)
#define STAGE_E (4 * TILE_E)
#define G_SMEM  (2 * STAGE_E * 2)
#define NCHUNK  (DD / 32)

__global__ __launch_bounds__(256) void qkv_gemm_mma(
    const __nv_bfloat16* __restrict__ Ahi, const __nv_bfloat16* __restrict__ Alo,
    const __nv_bfloat16* __restrict__ Whi_all,
    const __nv_bfloat16* __restrict__ Wlo_all,
    const float* __restrict__ bq, const float* __restrict__ bk,
    const float* __restrict__ bv,
    __nv_bfloat16* __restrict__ qh, __nv_bfloat16* __restrict__ ql,
    __nv_bfloat16* __restrict__ kh, __nv_bfloat16* __restrict__ kl,
    __nv_bfloat16* __restrict__ vh, __nv_bfloat16* __restrict__ vl)
{
    extern __shared__ __nv_bfloat16 gsm[];
    const uint32_t smb = smem_u32(gsm);

    const int z = blockIdx.z;
    const __nv_bfloat16* __restrict__ Whi = Whi_all + (size_t)z * DD * DD;
    const __nv_bfloat16* __restrict__ Wlo = Wlo_all + (size_t)z * DD * DD;
    const float* __restrict__ bias = (z == 0) ? bq : ((z == 1) ? bk : bv);
    __nv_bfloat16* dh = (z == 0) ? qh : ((z == 1) ? kh : vh);
    __nv_bfloat16* dl = (z == 0) ? ql : ((z == 1) ? kl : vl);
    const float scale = (z == 0) ? 0.125f : 1.0f;

    const int tid  = threadIdx.x;
    const int wid  = tid >> 5;
    const int lane = tid & 31;
    const int bm   = blockIdx.y * 128;
    const int bn   = blockIdx.x * 128;
    const int mrow0 = (wid & 3) * 32;
    const int ncol0 = (wid >> 2) * 64;
    const int lr0 = tid >> 2;
    const int lg  = tid & 3;

    float acc[2][8][4];
    #pragma unroll
    for (int i = 0; i < 2; i++)
        #pragma unroll
        for (int j = 0; j < 8; j++)
            #pragma unroll
            for (int u = 0; u < 4; u++) acc[i][j][u] = 0.f;

    const int lm  = lane >> 3;
    const int lr8 = lane & 7;
    const int a_row_off = (lm & 1) * 8 + lr8;
    const int a_col_off = (lm >> 1) * 8;
    const int b_row_off = (lm >> 1) * 8 + lr8;
    const int b_col_off = (lm & 1) * 8;

    auto load_chunk = [&](int c, int s) {
        const int k0 = c * 32;
        const uint32_t sbase = smb + (uint32_t)(s * STAGE_E) * 2;
        const __nv_bfloat16* srcs[4] = {
            Ahi + (size_t)bm * DD + k0, Alo + (size_t)bm * DD + k0,
            Whi + (size_t)bn * DD + k0, Wlo + (size_t)bn * DD + k0 };
        #pragma unroll
        for (int t4 = 0; t4 < 4; t4++) {
            #pragma unroll
            for (int it = 0; it < 2; it++) {
                int r = lr0 + it * 64;
                cpa16(sbase + (uint32_t)(t4 * TILE_E + r * TSTR + lg * 8) * 2,
                      srcs[t4] + (size_t)r * DD + lg * 8);
            }
        }
        CPA_COMMIT();
    };

    load_chunk(0, 0);
    CPA_WAIT(0);
    __syncthreads();

    for (int c = 0; c < NCHUNK; c++) {
        if (c + 1 < NCHUNK) {
            load_chunk(c + 1, (c + 1) & 1);
            CPA_WAIT(1);
        } else {
            CPA_WAIT(0);
        }
        __syncthreads();

        const uint32_t sbase = smb + (uint32_t)((c & 1) * STAGE_E) * 2;
        const uint32_t baseAhi = sbase;
        const uint32_t baseAlo = sbase + (uint32_t)TILE_E * 2;
        const uint32_t baseWhi = sbase + (uint32_t)(2 * TILE_E) * 2;
        const uint32_t baseWlo = sbase + (uint32_t)(3 * TILE_E) * 2;

        #pragma unroll
        for (int kk = 0; kk < 32; kk += 16) {
            uint32_t ah[2][4], al[2][4];
            #pragma unroll
            for (int mt2 = 0; mt2 < 2; mt2++) {
                uint32_t off = (uint32_t)((mrow0 + mt2 * 16 + a_row_off) * TSTR
                                          + kk + a_col_off) * 2;
                LDSM4(ah[mt2][0], ah[mt2][1], ah[mt2][2], ah[mt2][3],
                      baseAhi + off);
                LDSM4(al[mt2][0], al[mt2][1], al[mt2][2], al[mt2][3],
                      baseAlo + off);
            }
            uint32_t bh[16], bl[16];
            #pragma unroll
            for (int ng = 0; ng < 4; ng++) {
                uint32_t off = (uint32_t)((ncol0 + ng * 16 + b_row_off) * TSTR
                                          + kk + b_col_off) * 2;
                LDSM4(bh[ng*4+0], bh[ng*4+1], bh[ng*4+2], bh[ng*4+3],
                      baseWhi + off);
                LDSM4(bl[ng*4+0], bl[ng*4+1], bl[ng*4+2], bl[ng*4+3],
                      baseWlo + off);
            }
            #pragma unroll
            for (int mt2 = 0; mt2 < 2; mt2++) {
                #pragma unroll
                for (int nt = 0; nt < 8; nt++) {
                    int bi = (nt >> 1) * 4 + (nt & 1) * 2;
                    MMA16816(acc[mt2][nt], ah[mt2], bh[bi], bh[bi+1]);
                    MMA16816(acc[mt2][nt], ah[mt2], bl[bi], bl[bi+1]);
                    MMA16816(acc[mt2][nt], al[mt2], bh[bi], bh[bi+1]);
                }
            }
        }
        __syncthreads();
    }

    // epilogue: (acc+bias)*scale -> bf16 hi/lo pairs at [b,h,s,d]
    #pragma unroll
    for (int mt2 = 0; mt2 < 2; mt2++) {
        int grow0 = bm + mrow0 + mt2 * 16 + (lane >> 2);
        int b0 = grow0 >> 12;
        int s0 = grow0 & (SS - 1);
        #pragma unroll
        for (int nt = 0; nt < 8; nt++) {
            int gcol = bn + ncol0 + nt * 8 + 2 * (lane & 3);
            int head = gcol >> 6;
            int d    = gcol & 63;
            float2 bsv = *(const float2*)(bias + gcol);
            size_t idx = ((size_t)(b0 * NH + head) * SS + s0) * HD + d;
            float v0 = (acc[mt2][nt][0] + bsv.x) * scale;
            float v1 = (acc[mt2][nt][1] + bsv.y) * scale;
            float v2 = (acc[mt2][nt][2] + bsv.x) * scale;
            float v3 = (acc[mt2][nt][3] + bsv.y) * scale;
            uint32_t h01 = cvt_bf2(v1, v0);
            uint32_t l01 = cvt_bf2(v1 - bf2_hi(h01), v0 - bf2_lo(h01));
            uint32_t h23 = cvt_bf2(v3, v2);
            uint32_t l23 = cvt_bf2(v3 - bf2_hi(h23), v2 - bf2_lo(h23));
            *(uint32_t*)(dh + idx) = h01;
            *(uint32_t*)(dl + idx) = l01;
            *(uint32_t*)(dh + idx + (size_t)8 * HD) = h23;
            *(uint32_t*)(dl + idx + (size_t)8 * HD) = l23;
        }
    }
}

// ---------------------------------------------------------------------------
// Banded attention on tensor cores: 128-q tile, 10 key tiles, bf16 hi/lo,
// FA2 C-frag->A-frag register conversion (no smem roundtrip for P).
// ---------------------------------------------------------------------------
#define ASTR 72

__global__ __launch_bounds__(256, 2) void attn_mma(
    const __nv_bfloat16* __restrict__ qhi, const __nv_bfloat16* __restrict__ qlo,
    const __nv_bfloat16* __restrict__ khi, const __nv_bfloat16* __restrict__ klo,
    const __nv_bfloat16* __restrict__ vthi, const __nv_bfloat16* __restrict__ vtlo,
    const float* __restrict__ fmask, const unsigned char* __restrict__ imask,
    float* __restrict__ out)
{
    __shared__ __nv_bfloat16 sm[4 * 64 * ASTR];
    __shared__ float fmk[64];
    const uint32_t smb = smem_u32(sm);

    const int tid  = threadIdx.x;
    const int w    = tid >> 5;
    const int lane = tid & 31;
    const int bh   = blockIdx.y;
    const int b    = bh / NH;
    const int hh   = bh % NH;
    const int q0   = blockIdx.x * 128;

    const int lm  = lane >> 3;
    const int lr8 = lane & 7;
    const int a_row_off = (lm & 1) * 8 + lr8;
    const int a_col_off = (lm >> 1) * 8;
    const int b_row_off = (lm >> 1) * 8 + lr8;
    const int b_col_off = (lm & 1) * 8;
    const int gid = lane >> 2;
    const int tig = lane & 3;

    // ---- stage Q (hi rows 0-127 in regions 0-1, lo in regions 2-3) ----
    #pragma unroll
    for (int it = 0; it < 8; it++) {
        int c = it * 256 + tid;
        int hilo = c >> 10;
        int r    = (c >> 3) & 127;
        int col  = c & 7;
        const __nv_bfloat16* src = (hilo ? qlo : qhi)
            + ((size_t)bh * SS + q0 + r) * HD + col * 8;
        cpa16(smb + (uint32_t)(hilo * 128 * ASTR + r * ASTR + col * 8) * 2, src);
    }
    CPA_COMMIT();
    CPA_WAIT(0);
    __syncthreads();

    uint32_t qfh[16], qfl[16];
    #pragma unroll
    for (int kb = 0; kb < 4; kb++) {
        uint32_t off = (uint32_t)((w * 16 + a_row_off) * ASTR
                                  + kb * 16 + a_col_off) * 2;
        LDSM4(qfh[kb*4+0], qfh[kb*4+1], qfh[kb*4+2], qfh[kb*4+3], smb + off);
        LDSM4(qfl[kb*4+0], qfl[kb*4+1], qfl[kb*4+2], qfl[kb*4+3],
              smb + (uint32_t)(128 * ASTR) * 2 + off);
    }
    __syncthreads();       // Q buffer about to be reused for K/V

    float oacc[8][4];
    #pragma unroll
    for (int j = 0; j < 8; j++)
        #pragma unroll
        for (int u = 0; u < 4; u++) oacc[j][u] = 0.f;
    float rsum0 = 0.f, rsum1 = 0.f;

    const int row_lo = q0 + w * 16 + gid;
    const int row_hi = row_lo + 8;

    for (int t = 0; t < 10; t++) {
        const int kstart = q0 - WIN + t * 64;
        if (kstart < 0 || kstart >= SS) continue;
        const bool edge = (t < 2) || (t > 7);

        // fill KHI/KLO/VTHI/VTLO tiles (never OOB: kstart multiple of 64)
        #pragma unroll
        for (int it = 0; it < 8; it++) {
            int c    = it * 256 + tid;
            int tile = c >> 9;
            int r    = (c >> 3) & 63;
            int col  = c & 7;
            const __nv_bfloat16* src;
            if (tile == 0)
                src = khi + ((size_t)bh * SS + kstart + r) * HD + col * 8;
            else if (tile == 1)
                src = klo + ((size_t)bh * SS + kstart + r) * HD + col * 8;
            else if (tile == 2)
                src = vthi + ((size_t)bh * HD + r) * SS + kstart + col * 8;
            else
                src = vtlo + ((size_t)bh * HD + r) * SS + kstart + col * 8;
            cpa16(smb + (uint32_t)(tile * 64 * ASTR + r * ASTR + col * 8) * 2,
                  src);
        }
        CPA_COMMIT();
        if (tid < 64) {
            float mv = fmask[b * SS + kstart + tid];
            fmk[tid] = (mv != 0.f) ? -1e30f : 0.f;
        }
        CPA_WAIT(0);
        __syncthreads();

        // ---- S = Q K^T (3-pass hi/lo) ----
        float s[8][4];
        #pragma unroll
        for (int j = 0; j < 8; j++)
            #pragma unroll
            for (int u = 0; u < 4; u++) s[j][u] = 0.f;
        #pragma unroll
        for (int kb = 0; kb < 4; kb++) {
            #pragma unroll
            for (int ng = 0; ng < 4; ng++) {
                uint32_t off = (uint32_t)((ng * 16 + b_row_off) * ASTR
                                          + kb * 16 + b_col_off) * 2;
                uint32_t kh0, kh1, kh2, kh3, kl0, kl1, kl2, kl3;
                LDSM4(kh0, kh1, kh2, kh3, smb + off);
                LDSM4(kl0, kl1, kl2, kl3,
                      smb + (uint32_t)(64 * ASTR) * 2 + off);
                MMA16816(s[2*ng],   &qfh[kb*4], kh0, kh1);
                MMA16816(s[2*ng],   &qfh[kb*4], kl0, kl1);
                MMA16816(s[2*ng],   &qfl[kb*4], kh0, kh1);
                MMA16816(s[2*ng+1], &qfh[kb*4], kh2, kh3);
                MMA16816(s[2*ng+1], &qfh[kb*4], kl2, kl3);
                MMA16816(s[2*ng+1], &qfl[kb*4], kh2, kh3);
            }
        }

        // ---- exp + window mask + row sums (fp32, C-frag layout) ----
        float rl = 0.f, rh = 0.f;
        #pragma unroll
        for (int nf = 0; nf < 8; nf++) {
            int key0 = kstart + nf * 8 + 2 * tig;
            float fm0 = fmk[nf * 8 + 2 * tig];
            float fm1 = fmk[nf * 8 + 2 * tig + 1];
            float p0 = expfast(s[nf][0] + fm0);
            float p1 = expfast(s[nf][1] + fm1);
            float p2 = expfast(s[nf][2] + fm0);
            float p3 = expfast(s[nf][3] + fm1);
            if (edge) {
                if (abs(key0     - row_lo) > WIN) p0 = 0.f;
                if (abs(key0 + 1 - row_lo) > WIN) p1 = 0.f;
                if (abs(key0     - row_hi) > WIN) p2 = 0.f;
                if (abs(key0 + 1 - row_hi) > WIN) p3 = 0.f;
            }
            s[nf][0] = p0; s[nf][1] = p1; s[nf][2] = p2; s[nf][3] = p3;
            rl += p0 + p1;
            rh += p2 + p3;
        }
        rl += __shfl_xor_sync(0xffffffffu, rl, 1);
        rl += __shfl_xor_sync(0xffffffffu, rl, 2);
        rh += __shfl_xor_sync(0xffffffffu, rh, 1);
        rh += __shfl_xor_sync(0xffffffffu, rh, 2);
        rsum0 += rl;
        rsum1 += rh;

        // ---- P -> bf16 hi/lo A-frags (pure register conversion) ----
        uint32_t aph[4][4], apl[4][4];
        #pragma unroll
        for (int j = 0; j < 4; j++) {
            uint32_t h;
            h = cvt_bf2(s[2*j][1], s[2*j][0]);
            aph[j][0] = h;
            apl[j][0] = cvt_bf2(s[2*j][1] - bf2_hi(h), s[2*j][0] - bf2_lo(h));
            h = cvt_bf2(s[2*j][3], s[2*j][2]);
            aph[j][1] = h;
            apl[j][1] = cvt_bf2(s[2*j][3] - bf2_hi(h), s[2*j][2] - bf2_lo(h));
            h = cvt_bf2(s[2*j+1][1], s[2*j+1][0]);
            aph[j][2] = h;
            apl[j][2] = cvt_bf2(s[2*j+1][1] - bf2_hi(h), s[2*j+1][0] - bf2_lo(h));
            h = cvt_bf2(s[2*j+1][3], s[2*j+1][2]);
            aph[j][3] = h;
            apl[j][3] = cvt_bf2(s[2*j+1][3] - bf2_hi(h), s[2*j+1][2] - bf2_lo(h));
        }

        // ---- O += P V  (VT in smem, 3-pass hi/lo) ----
        #pragma unroll
        for (int j = 0; j < 4; j++) {
            #pragma unroll
            for (int nb = 0; nb < 4; nb++) {
                uint32_t off = (uint32_t)((nb * 16 + b_row_off) * ASTR
                                          + j * 16 + b_col_off) * 2;
                uint32_t vh0, vh1, vh2, vh3, vl0, vl1, vl2, vl3;
                LDSM4(vh0, vh1, vh2, vh3,
                      smb + (uint32_t)(2 * 64 * ASTR) * 2 + off);
                LDSM4(vl0, vl1, vl2, vl3,
                      smb + (uint32_t)(3 * 64 * ASTR) * 2 + off);
                MMA16816(oacc[2*nb],   aph[j], vh0, vh1);
                MMA16816(oacc[2*nb],   aph[j], vl0, vl1);
                MMA16816(oacc[2*nb],   apl[j], vh0, vh1);
                MMA16816(oacc[2*nb+1], aph[j], vh2, vh3);
                MMA16816(oacc[2*nb+1], aph[j], vl2, vl3);
                MMA16816(oacc[2*nb+1], apl[j], vh2, vh3);
            }
        }
        __syncthreads();
    }

    // ---- epilogue ----
    float inv0 = 1.f / rsum0;
    float inv1 = 1.f / rsum1;
    if (imask[b * SS + row_lo]) inv0 = 0.f;
    if (imask[b * SS + row_hi]) inv1 = 0.f;
    float* o0 = out + ((size_t)b * SS + row_lo) * DD + hh * HD + 2 * tig;
    float* o1 = out + ((size_t)b * SS + row_hi) * DD + hh * HD + 2 * tig;
    #pragma unroll
    for (int nf = 0; nf < 8; nf++) {
        float2 w0 = make_float2(oacc[nf][0] * inv0, oacc[nf][1] * inv0);
        float2 w1 = make_float2(oacc[nf][2] * inv1, oacc[nf][3] * inv1);
        *(float2*)(o0 + nf * 8) = w0;
        *(float2*)(o1 + nf * 8) = w1;
    }
}

// ---------------------------------------------------------------------------
extern "C" void kernel_launch(void* const* d_in, const int* in_sizes, int n_in,
                              void* d_out, int out_size)
{
    const float* hidden = (const float*)d_in[0];
    const float* amask  = (const float*)d_in[1];
    const unsigned char* imask = (const unsigned char*)d_in[2];
    const float* Wq = (const float*)d_in[3];
    const float* bq = (const float*)d_in[4];
    const float* Wk = (const float*)d_in[5];
    const float* bk = (const float*)d_in[6];
    const float* Wv = (const float*)d_in[7];
    const float* bv = (const float*)d_in[8];
    float* out = (float*)d_out;

    __nv_bfloat16 *pahi, *palo, *pwhi, *pwlo;
    __nv_bfloat16 *pqh, *pql, *pkh, *pkl, *pvh, *pvl, *pvth, *pvtl;
    cudaGetSymbolAddress((void**)&pahi, g_ahi);
    cudaGetSymbolAddress((void**)&palo, g_alo);
    cudaGetSymbolAddress((void**)&pwhi, g_wthi);
    cudaGetSymbolAddress((void**)&pwlo, g_wtlo);
    cudaGetSymbolAddress((void**)&pqh, g_qhi);
    cudaGetSymbolAddress((void**)&pql, g_qlo);
    cudaGetSymbolAddress((void**)&pkh, g_khi);
    cudaGetSymbolAddress((void**)&pkl, g_klo);
    cudaGetSymbolAddress((void**)&pvh, g_vhi);
    cudaGetSymbolAddress((void**)&pvl, g_vlo);
    cudaGetSymbolAddress((void**)&pvth, g_vthi);
    cudaGetSymbolAddress((void**)&pvtl, g_vtlo);

    cudaFuncSetAttribute(qkv_gemm_mma,
                         cudaFuncAttributeMaxDynamicSharedMemorySize, G_SMEM);

    // prep: bf16 hi/lo splits
    asplit<<<592, 256>>>((const float4*)hidden,
                         (__nv_bfloat162*)pahi, (__nv_bfloat162*)palo,
                         BB * SS * DD / 4);
    dim3 wb(32, 8), wg(DD / 32, DD / 32);
    wsplit<<<wg, wb>>>(Wq, pwhi + 0 * DD * DD, pwlo + 0 * DD * DD);
    wsplit<<<wg, wb>>>(Wk, pwhi + 1 * DD * DD, pwlo + 1 * DD * DD);
    wsplit<<<wg, wb>>>(Wv, pwhi + 2 * DD * DD, pwlo + 2 * DD * DD);

    // tensor-core QKV GEMMs -> bf16 hi/lo outputs
    dim3 gg(DD / 128, (BB * SS) / 128, 3);
    qkv_gemm_mma<<<gg, 256, G_SMEM>>>(pahi, palo, pwhi, pwlo,
                                      bq, bk, bv,
                                      pqh, pql, pkh, pkl, pvh, pvl);

    // V transpose for PV mma B-operand
    dim3 vg(SS / 64, BH, 2);
    vtrans<<<vg, 256>>>(pvh, pvl, pvth, pvtl);

    // tensor-core banded attention
    dim3 agrid(SS / 128, BH);
    attn_mma<<<agrid, 256>>>(pqh, pql, pkh, pkl, pvth, pvtl,
                             amask, imask, out);
}